// round 10
// baseline (speedup 1.0000x reference)
#include <cuda_runtime.h>
#include <math.h>

#define Bz 64
#define Tn 512
#define In 256
#define Hn 1024
#define On 512
#define Gn 4096
#define NSTEPS 100
#define KB 64            // k-slice per staging round

// packed f32x2 FMA (sm_103a; only reachable via PTX)
#define FMA2(d, a, b) asm("fma.rn.f32x2 %0, %1, %2, %3;" \
                          : "=l"(d) : "l"(a), "l"(b), "l"(d))

// ---------------- device scratch (static, allocation-free) ----------------
__device__ float g_h[2][Bz * Hn];
__device__ float g_c[Bz * Hn];
__device__ float g_be[Gn];
__device__ float g_bd[Gn];
__device__ float g_sd[Gn];
__device__ float g_tokf[Bz];
__device__ float g_part[4][Bz * On];

__global__ void prep_kernel(const float* __restrict__ ebih, const float* __restrict__ ebhh,
                            const float* __restrict__ dbih, const float* __restrict__ dbhh,
                            const float* __restrict__ dWih) {
    int i = blockIdx.x * blockDim.x + threadIdx.x;
    if (i < Gn) {
        g_be[i] = ebih[i] + ebhh[i];
        g_bd[i] = dbih[i] + dbhh[i];
        float s = 0.f;
        const float* row = dWih + (size_t)i * On;
        #pragma unroll 8
        for (int j = 0; j < On; j++) s += row[j];
        g_sd[i] = s;
    }
    if (i < Bz * Hn) { g_h[0][i] = 0.f; g_c[i] = 0.f; }
    if (i < Bz) g_tokf[i] = 0.f;
}

__device__ __forceinline__ float sigf(float x) { return 1.f / (1.f + expf(-x)); }

// ---------------------------------------------------------------------------
// Fused LSTM step v2: k-major smem + duplicated W + packed f32x2 FMA.
// Block = 64 batch rows x 32 gate cols (4 gates x 8 h-cols), grid = 128.
// Per thread: 4 rows x 2 cols; inner loop = 2x LDS.128 + 4x fma.rn.f32x2 per k.
// ---------------------------------------------------------------------------
#define WS_STRIDE 68     // 68*4B = 272B, 16B-aligned rows, staggered banks

template <bool ENC>
__global__ __launch_bounds__(256) void lstm_step(const float* __restrict__ Wih,
                                                 const float* __restrict__ xbase,
                                                 const float* __restrict__ Whh,
                                                 int insel) {
    __shared__ __align__(16) float As[KB * 64];          // As[kk][row], 16 KB
    __shared__ __align__(16) float Ws[KB * WS_STRIDE];   // Ws[kk][2c+{0,1}] dup, 17 KB
    __shared__ float Gs[64 * 33];                        // gate staging, 8.4 KB

    const int tid = threadIdx.x;
    const int tx = tid & 15;        // col group (2 cols)
    const int ty = tid >> 4;        // row group (4 rows)
    const int col_base = blockIdx.x * 8;

    // staging maps
    const int arow = tid & 63;              // A staging: row
    const int acq  = tid >> 6;              // A staging: k-quarter (16 k each)
    const int wrow = tid >> 3;              // W staging: local col c (0..31)
    const int wkq  = tid & 7;               // W staging: k-octet (8 k each)
    const int wgr  = (wrow >> 3) * Hn + col_base + (wrow & 7);  // gate row

    unsigned long long acc00 = 0, acc10 = 0, acc01 = 0, acc11 = 0;
    const float* hin = g_h[insel];

    for (int seg = ENC ? 0 : 1; seg < 2; ++seg) {
        const float* A;
        const float* W;
        long arst;
        int kdim;
        if (seg == 0) { A = xbase; arst = (long)Tn * In; W = Wih; kdim = In; }
        else          { A = hin;   arst = Hn;            W = Whh; kdim = Hn; }

        const float* asrc_row = A + (size_t)arow * arst;
        const float* wsrc_row = W + (size_t)wgr * kdim;

        for (int k0 = 0; k0 < kdim; k0 += KB) {
            // ---- stage A (k-major transpose): 4x LDG.128 + 16 STS / thread ----
            {
                const float* src = asrc_row + k0 + acq * 16;
                #pragma unroll
                for (int j = 0; j < 4; j++) {
                    float4 v = *(const float4*)(src + 4 * j);
                    int kk = acq * 16 + 4 * j;
                    As[(kk + 0) * 64 + arow] = v.x;
                    As[(kk + 1) * 64 + arow] = v.y;
                    As[(kk + 2) * 64 + arow] = v.z;
                    As[(kk + 3) * 64 + arow] = v.w;
                }
            }
            // ---- stage W duplicated: 2x LDG.128 + 16 STS / thread ----
            {
                const float* src = wsrc_row + k0 + wkq * 8;
                float4 v0 = *(const float4*)(src);
                float4 v1 = *(const float4*)(src + 4);
                int kk = wkq * 8;
                float wv[8] = {v0.x, v0.y, v0.z, v0.w, v1.x, v1.y, v1.z, v1.w};
                #pragma unroll
                for (int e = 0; e < 8; e++) {
                    float* d = &Ws[(kk + e) * WS_STRIDE + 2 * wrow];
                    d[0] = wv[e];
                    d[1] = wv[e];
                }
            }
            __syncthreads();

            // ---- compute: per kk, 2x LDS.128 + 4x fma.rn.f32x2 ----
            const float* ap = &As[ty * 4];
            const float* wp = &Ws[tx * 4];
            #pragma unroll 8
            for (int kk = 0; kk < KB; ++kk) {
                ulonglong2 av = *(const ulonglong2*)(ap + kk * 64);
                ulonglong2 wv = *(const ulonglong2*)(wp + kk * WS_STRIDE);
                FMA2(acc00, av.x, wv.x);   // rows ty*4+0,1  col tx*2+0
                FMA2(acc10, av.y, wv.x);   // rows ty*4+2,3  col tx*2+0
                FMA2(acc01, av.x, wv.y);   // rows ty*4+0,1  col tx*2+1
                FMA2(acc11, av.y, wv.y);   // rows ty*4+2,3  col tx*2+1
            }
            __syncthreads();
        }
    }

    // ---- unpack accumulators -> Gs (same layout as v1) ----
    float accf[4][2];
    asm("mov.b64 {%0,%1}, %2;" : "=f"(accf[0][0]), "=f"(accf[1][0]) : "l"(acc00));
    asm("mov.b64 {%0,%1}, %2;" : "=f"(accf[2][0]), "=f"(accf[3][0]) : "l"(acc10));
    asm("mov.b64 {%0,%1}, %2;" : "=f"(accf[0][1]), "=f"(accf[1][1]) : "l"(acc01));
    asm("mov.b64 {%0,%1}, %2;" : "=f"(accf[2][1]), "=f"(accf[3][1]) : "l"(acc11));

    #pragma unroll
    for (int i = 0; i < 4; i++) {
        int r = ty * 4 + i;
        #pragma unroll
        for (int j = 0; j < 2; j++) {
            int oc = tx * 2 + j;
            int gr = (oc >> 3) * Hn + col_base + (oc & 7);
            float g = accf[i][j] + (ENC ? g_be[gr] : g_bd[gr]);
            if (!ENC) g += g_tokf[r] * g_sd[gr];   // rank-1 token-input term
            Gs[r * 33 + oc] = g;
        }
    }
    __syncthreads();

    // ---- cell update: 512 (b, hc) pairs, 2 per thread ----
    const int outsel = insel ^ 1;
    #pragma unroll
    for (int p0 = 0; p0 < 2; ++p0) {
        int p = tid + p0 * 256;
        int b = p >> 3;
        int hc = p & 7;
        float gi = Gs[b * 33 + hc];
        float gf = Gs[b * 33 + 8 + hc];
        float gg = Gs[b * 33 + 16 + hc];
        float go = Gs[b * 33 + 24 + hc];
        int col = col_base + hc;
        float cprev = g_c[b * Hn + col];
        float cc = sigf(gf) * cprev + sigf(gi) * tanhf(gg);
        g_c[b * Hn + col] = cc;
        g_h[outsel][b * Hn + col] = sigf(go) * tanhf(cc);
    }
}

// fc partial GEMM: grid (32 oc-tiles of 16, 4 K-quarters), 256 threads.
__global__ __launch_bounds__(256) void fc_partial(const float* __restrict__ fcW, int hsel) {
    __shared__ float Ah[64 * 36];
    __shared__ float Wf[16 * 33];
    const int tid = threadIdx.x;
    const int tx = tid & 15;   // one output col each
    const int ty = tid >> 4;   // 4 batch rows each
    const int oc0 = blockIdx.x * 16;
    const int kq = blockIdx.y;
    const float* hin = g_h[hsel];
    float acc[4] = {};

    for (int k0 = kq * 256; k0 < kq * 256 + 256; k0 += 32) {
        {
            int row = tid >> 2;
            int c0 = (tid & 3) * 8;
            const float* src = hin + (size_t)row * Hn + k0 + c0;
            *(float4*)&Ah[row * 36 + c0]     = *(const float4*)(src);
            *(float4*)&Ah[row * 36 + c0 + 4] = *(const float4*)(src + 4);
        }
        if (tid < 128) {
            int wrow = tid >> 3;
            int wc = (tid & 7) * 4;
            float4 v = *(const float4*)(fcW + (size_t)(oc0 + wrow) * Hn + k0 + wc);
            Wf[wrow * 33 + wc + 0] = v.x;
            Wf[wrow * 33 + wc + 1] = v.y;
            Wf[wrow * 33 + wc + 2] = v.z;
            Wf[wrow * 33 + wc + 3] = v.w;
        }
        __syncthreads();
        #pragma unroll
        for (int kk = 0; kk < 32; ++kk) {
            float b = Wf[tx * 33 + kk];
            acc[0] += Ah[(ty * 4 + 0) * 36 + kk] * b;
            acc[1] += Ah[(ty * 4 + 1) * 36 + kk] * b;
            acc[2] += Ah[(ty * 4 + 2) * 36 + kk] * b;
            acc[3] += Ah[(ty * 4 + 3) * 36 + kk] * b;
        }
        __syncthreads();
    }
    #pragma unroll
    for (int i = 0; i < 4; i++)
        g_part[kq][(size_t)(ty * 4 + i) * On + oc0 + tx] = acc[i];
}

// argmax per batch row, first-index tie-break (matches jnp.argmax). f32 output.
__global__ __launch_bounds__(128) void argmax_kernel(const float* __restrict__ fcb,
                                                     float* __restrict__ out, int step) {
    const int b = blockIdx.x;
    const int tid = threadIdx.x;
    __shared__ float sv[128];
    __shared__ int si[128];
    float bestv = -3.4e38f;
    int besti = 0;
    for (int o = tid; o < On; o += 128) {
        float v = fcb[o] + g_part[0][(size_t)b * On + o] + g_part[1][(size_t)b * On + o]
                         + g_part[2][(size_t)b * On + o] + g_part[3][(size_t)b * On + o];
        if (v > bestv) { bestv = v; besti = o; }   // ascending o => first index kept
    }
    sv[tid] = bestv;
    si[tid] = besti;
    __syncthreads();
    for (int s = 64; s > 0; s >>= 1) {
        if (tid < s) {
            float v2 = sv[tid + s];
            int i2 = si[tid + s];
            if (v2 > sv[tid] || (v2 == sv[tid] && i2 < si[tid])) { sv[tid] = v2; si[tid] = i2; }
        }
        __syncthreads();
    }
    if (tid == 0) {
        g_tokf[b] = (float)si[0];
        out[b * NSTEPS + step] = (float)si[0];
    }
}

extern "C" void kernel_launch(void* const* d_in, const int* in_sizes, int n_in,
                              void* d_out, int out_size) {
    // Insertion-order binding (confirmed by diagnostics):
    const float* inputs  = (const float*)d_in[0];
    const float* enc_Wih = (const float*)d_in[1];
    const float* enc_Whh = (const float*)d_in[2];
    const float* enc_bih = (const float*)d_in[3];
    const float* enc_bhh = (const float*)d_in[4];
    const float* dec_Wih = (const float*)d_in[5];
    const float* dec_Whh = (const float*)d_in[6];
    const float* dec_bih = (const float*)d_in[7];
    const float* dec_bhh = (const float*)d_in[8];
    const float* fc_W    = (const float*)d_in[9];
    const float* fc_b    = (const float*)d_in[10];
    float* out = (float*)d_out;

    prep_kernel<<<256, 256>>>(enc_bih, enc_bhh, dec_bih, dec_bhh, dec_Wih);

    // encoder: 512 sequential steps; x_t rows are strided (inputs is [B, T, I])
    for (int t = 0; t < Tn; t++)
        lstm_step<true><<<128, 256>>>(enc_Wih, inputs + (size_t)t * In, enc_Whh, t & 1);

    // decoder: 100 autoregressive steps
    for (int s = 0; s < NSTEPS; s++) {
        lstm_step<false><<<128, 256>>>(nullptr, nullptr, dec_Whh, s & 1);
        fc_partial<<<dim3(32, 4), 256>>>(fc_W, (s & 1) ^ 1);
        argmax_kernel<<<64, 128>>>(fc_b, out, s);
    }
}

// round 11
// speedup vs baseline: 1.4980x; 1.4980x over previous
#include <cuda_runtime.h>
#include <math.h>

#define Bz 64
#define Tn 512
#define In 256
#define Hn 1024
#define On 512
#define Gn 4096
#define NSTEPS 100

// ---------------- device scratch (static, allocation-free) ----------------
__device__ float g_h[2][Bz * Hn];
__device__ float g_c[Bz * Hn];
__device__ float g_be[Gn];
__device__ float g_bd[Gn];
__device__ float g_sd[Gn];
__device__ float g_tokf[Bz];
__device__ float g_part[4][Bz * On];

__global__ void prep_kernel(const float* __restrict__ ebih, const float* __restrict__ ebhh,
                            const float* __restrict__ dbih, const float* __restrict__ dbhh,
                            const float* __restrict__ dWih) {
    int i = blockIdx.x * blockDim.x + threadIdx.x;
    if (i < Gn) {
        g_be[i] = ebih[i] + ebhh[i];
        g_bd[i] = dbih[i] + dbhh[i];
        float s = 0.f;
        const float* row = dWih + (size_t)i * On;
        #pragma unroll 8
        for (int j = 0; j < On; j++) s += row[j];
        g_sd[i] = s;
    }
    if (i < Bz * Hn) { g_h[0][i] = 0.f; g_c[i] = 0.f; }
    if (i < Bz) g_tokf[i] = 0.f;
}

__device__ __forceinline__ float sigf(float x) { return 1.f / (1.f + expf(-x)); }

// ---------------------------------------------------------------------------
// Fused LSTM step v3: v1 data layout + 512 threads with K-split.
// Block = 64 batch x 32 gate cols (4 gates x 8 h-cols), grid = 128.
// Two 256-thread groups each run the v1 inner loop on half of each 32-k slice;
// partials are combined through smem. 16 warps/SM for latency hiding.
// ---------------------------------------------------------------------------
template <bool ENC>
__global__ __launch_bounds__(512) void lstm_step(const float* __restrict__ Wih,
                                                 const float* __restrict__ xbase,
                                                 const float* __restrict__ Whh,
                                                 int insel) {
    __shared__ float As[64 * 36];     // A tile [64 rows][32 k], pad 36
    __shared__ float Ws[32 * 33];     // W tile [32 gate cols][32 k], pad 33
    __shared__ float Gp[64 * 32];     // group-1 partial accumulators
    __shared__ float Gs[64 * 33];     // gates staging for cell update

    const int tid = threadIdx.x;
    const int sub = tid & 255;
    const int grp = tid >> 8;          // 0 or 1: which k-half of each slice
    const int tx = sub & 15;           // 2 cols
    const int ty = sub >> 4;           // 4 rows
    const int col_base = blockIdx.x * 8;
    const int kofs = grp * 16;         // this group's k-offset within a slice

    float acc[4][2] = {};
    const float* hin = g_h[insel];

    for (int seg = ENC ? 0 : 1; seg < 2; ++seg) {
        const float* A;
        const float* W;
        long arst;
        int kdim;
        if (seg == 0) { A = xbase; arst = (long)Tn * In; W = Wih; kdim = In; }
        else          { A = hin;   arst = Hn;            W = Whh; kdim = Hn; }

        for (int k0 = 0; k0 < kdim; k0 += 32) {
            // ---- stage A tile 64x32: 512 threads x 1 float4 ----
            {
                int row = tid >> 3;
                int c0 = (tid & 7) * 4;
                *(float4*)&As[row * 36 + c0] =
                    *(const float4*)(A + (size_t)row * arst + k0 + c0);
            }
            // ---- stage W tile 32x32: first 256 threads x 1 float4 ----
            if (tid < 256) {
                int wrow = tid >> 3;
                int wc = (tid & 7) * 4;
                int gr = (wrow >> 3) * Hn + col_base + (wrow & 7);
                float4 v = *(const float4*)(W + (size_t)gr * kdim + k0 + wc);
                Ws[wrow * 33 + wc + 0] = v.x;
                Ws[wrow * 33 + wc + 1] = v.y;
                Ws[wrow * 33 + wc + 2] = v.z;
                Ws[wrow * 33 + wc + 3] = v.w;
            }
            __syncthreads();

            // ---- v1 inner loop on this group's 16-k half ----
            #pragma unroll
            for (int kk = kofs; kk < kofs + 16; ++kk) {
                float a0 = As[(ty * 4 + 0) * 36 + kk];
                float a1 = As[(ty * 4 + 1) * 36 + kk];
                float a2 = As[(ty * 4 + 2) * 36 + kk];
                float a3 = As[(ty * 4 + 3) * 36 + kk];
                float b0 = Ws[(tx * 2 + 0) * 33 + kk];
                float b1 = Ws[(tx * 2 + 1) * 33 + kk];
                acc[0][0] += a0 * b0; acc[0][1] += a0 * b1;
                acc[1][0] += a1 * b0; acc[1][1] += a1 * b1;
                acc[2][0] += a2 * b0; acc[2][1] += a2 * b1;
                acc[3][0] += a3 * b0; acc[3][1] += a3 * b1;
            }
            __syncthreads();
        }
    }

    // ---- combine group partials ----
    if (grp == 1) {
        #pragma unroll
        for (int i = 0; i < 4; i++)
            #pragma unroll
            for (int j = 0; j < 2; j++)
                Gp[(ty * 4 + i) * 32 + tx * 2 + j] = acc[i][j];
    }
    __syncthreads();

    if (grp == 0) {
        #pragma unroll
        for (int i = 0; i < 4; i++) {
            int r = ty * 4 + i;
            #pragma unroll
            for (int j = 0; j < 2; j++) {
                int oc = tx * 2 + j;
                int gr = (oc >> 3) * Hn + col_base + (oc & 7);
                float g = acc[i][j] + Gp[r * 32 + oc] + (ENC ? g_be[gr] : g_bd[gr]);
                if (!ENC) g += g_tokf[r] * g_sd[gr];   // rank-1 token-input term
                Gs[r * 33 + oc] = g;
            }
        }
    }
    __syncthreads();

    // ---- cell update: 512 (b, hc) pairs, one per thread ----
    const int outsel = insel ^ 1;
    {
        int b = tid >> 3;
        int hc = tid & 7;
        float gi = Gs[b * 33 + hc];
        float gf = Gs[b * 33 + 8 + hc];
        float gg = Gs[b * 33 + 16 + hc];
        float go = Gs[b * 33 + 24 + hc];
        int col = col_base + hc;
        float cprev = g_c[b * Hn + col];
        float cc = sigf(gf) * cprev + sigf(gi) * tanhf(gg);
        g_c[b * Hn + col] = cc;
        g_h[outsel][b * Hn + col] = sigf(go) * tanhf(cc);
    }
}

// fc partial GEMM: grid (32 oc-tiles of 16, 4 K-quarters), 256 threads.
__global__ __launch_bounds__(256) void fc_partial(const float* __restrict__ fcW, int hsel) {
    __shared__ float Ah[64 * 36];
    __shared__ float Wf[16 * 33];
    const int tid = threadIdx.x;
    const int tx = tid & 15;   // one output col each
    const int ty = tid >> 4;   // 4 batch rows each
    const int oc0 = blockIdx.x * 16;
    const int kq = blockIdx.y;
    const float* hin = g_h[hsel];
    float acc[4] = {};

    for (int k0 = kq * 256; k0 < kq * 256 + 256; k0 += 32) {
        {
            int row = tid >> 2;
            int c0 = (tid & 3) * 8;
            const float* src = hin + (size_t)row * Hn + k0 + c0;
            *(float4*)&Ah[row * 36 + c0]     = *(const float4*)(src);
            *(float4*)&Ah[row * 36 + c0 + 4] = *(const float4*)(src + 4);
        }
        if (tid < 128) {
            int wrow = tid >> 3;
            int wc = (tid & 7) * 4;
            float4 v = *(const float4*)(fcW + (size_t)(oc0 + wrow) * Hn + k0 + wc);
            Wf[wrow * 33 + wc + 0] = v.x;
            Wf[wrow * 33 + wc + 1] = v.y;
            Wf[wrow * 33 + wc + 2] = v.z;
            Wf[wrow * 33 + wc + 3] = v.w;
        }
        __syncthreads();
        #pragma unroll
        for (int kk = 0; kk < 32; ++kk) {
            float b = Wf[tx * 33 + kk];
            acc[0] += Ah[(ty * 4 + 0) * 36 + kk] * b;
            acc[1] += Ah[(ty * 4 + 1) * 36 + kk] * b;
            acc[2] += Ah[(ty * 4 + 2) * 36 + kk] * b;
            acc[3] += Ah[(ty * 4 + 3) * 36 + kk] * b;
        }
        __syncthreads();
    }
    #pragma unroll
    for (int i = 0; i < 4; i++)
        g_part[kq][(size_t)(ty * 4 + i) * On + oc0 + tx] = acc[i];
}

// argmax per batch row, first-index tie-break (matches jnp.argmax). f32 output.
__global__ __launch_bounds__(128) void argmax_kernel(const float* __restrict__ fcb,
                                                     float* __restrict__ out, int step) {
    const int b = blockIdx.x;
    const int tid = threadIdx.x;
    __shared__ float sv[128];
    __shared__ int si[128];
    float bestv = -3.4e38f;
    int besti = 0;
    for (int o = tid; o < On; o += 128) {
        float v = fcb[o] + g_part[0][(size_t)b * On + o] + g_part[1][(size_t)b * On + o]
                         + g_part[2][(size_t)b * On + o] + g_part[3][(size_t)b * On + o];
        if (v > bestv) { bestv = v; besti = o; }   // ascending o => first index kept
    }
    sv[tid] = bestv;
    si[tid] = besti;
    __syncthreads();
    for (int s = 64; s > 0; s >>= 1) {
        if (tid < s) {
            float v2 = sv[tid + s];
            int i2 = si[tid + s];
            if (v2 > sv[tid] || (v2 == sv[tid] && i2 < si[tid])) { sv[tid] = v2; si[tid] = i2; }
        }
        __syncthreads();
    }
    if (tid == 0) {
        g_tokf[b] = (float)si[0];
        out[b * NSTEPS + step] = (float)si[0];
    }
}

extern "C" void kernel_launch(void* const* d_in, const int* in_sizes, int n_in,
                              void* d_out, int out_size) {
    // Insertion-order binding (confirmed by diagnostics):
    const float* inputs  = (const float*)d_in[0];
    const float* enc_Wih = (const float*)d_in[1];
    const float* enc_Whh = (const float*)d_in[2];
    const float* enc_bih = (const float*)d_in[3];
    const float* enc_bhh = (const float*)d_in[4];
    const float* dec_Wih = (const float*)d_in[5];
    const float* dec_Whh = (const float*)d_in[6];
    const float* dec_bih = (const float*)d_in[7];
    const float* dec_bhh = (const float*)d_in[8];
    const float* fc_W    = (const float*)d_in[9];
    const float* fc_b    = (const float*)d_in[10];
    float* out = (float*)d_out;

    prep_kernel<<<256, 256>>>(enc_bih, enc_bhh, dec_bih, dec_bhh, dec_Wih);

    // encoder: 512 sequential steps; x_t rows are strided (inputs is [B, T, I])
    for (int t = 0; t < Tn; t++)
        lstm_step<true><<<128, 512>>>(enc_Wih, inputs + (size_t)t * In, enc_Whh, t & 1);

    // decoder: 100 autoregressive steps
    for (int s = 0; s < NSTEPS; s++) {
        lstm_step<false><<<128, 512>>>(nullptr, nullptr, dec_Whh, s & 1);
        fc_partial<<<dim3(32, 4), 256>>>(fc_W, (s & 1) ^ 1);
        argmax_kernel<<<64, 128>>>(fc_b, out, s);
    }
}

// round 12
// speedup vs baseline: 1.7573x; 1.1731x over previous
#include <cuda_runtime.h>
#include <math.h>

#define Bz 64
#define Tn 512
#define In 256
#define Hn 1024
#define On 512
#define Gn 4096
#define NSTEPS 100

// packed f32x2 FMA (sm_103a; PTX-only)
#define FMA2(d, a, b) asm("fma.rn.f32x2 %0, %1, %2, %0;" : "+l"(d) : "l"(a), "l"(b))

// ---------------- device scratch (static, allocation-free) ----------------
__device__ float g_h[2][Bz * Hn];
__device__ float g_c[Bz * Hn];
__device__ float g_be[Gn];
__device__ float g_bd[Gn];
__device__ float g_sd[Gn];
__device__ float g_tokf[Bz];
__device__ float g_part[4][Bz * On];

__global__ void prep_kernel(const float* __restrict__ ebih, const float* __restrict__ ebhh,
                            const float* __restrict__ dbih, const float* __restrict__ dbhh,
                            const float* __restrict__ dWih) {
    int i = blockIdx.x * blockDim.x + threadIdx.x;
    if (i < Gn) {
        g_be[i] = ebih[i] + ebhh[i];
        g_bd[i] = dbih[i] + dbhh[i];
        float s = 0.f;
        const float* row = dWih + (size_t)i * On;
        #pragma unroll 8
        for (int j = 0; j < On; j++) s += row[j];
        g_sd[i] = s;
    }
    if (i < Bz * Hn) { g_h[0][i] = 0.f; g_c[i] = 0.f; }
    if (i < Bz) g_tokf[i] = 0.f;
}

__device__ __forceinline__ float sigf(float x) { return 1.f / (1.f + expf(-x)); }

// ---------------------------------------------------------------------------
// Fused LSTM step v4: v3 tiling (512 thr, K-split x2) + double-buffered slices
// + packed f32x2 FMA over k-pairs. Block = 64 batch x 32 gate cols, grid = 128.
// Inner loop per 2k: 6x LDS.64 + 8x fma.rn.f32x2. One barrier per 32-k slice.
// ---------------------------------------------------------------------------
#define WSS 34   // Ws row stride (even -> 8B-aligned float2 for odd cols)

template <bool ENC>
__global__ __launch_bounds__(512) void lstm_step(const float* __restrict__ Wih,
                                                 const float* __restrict__ xbase,
                                                 const float* __restrict__ Whh,
                                                 int insel) {
    __shared__ __align__(16) float As[2][64 * 36];   // [row][k] per buffer
    __shared__ __align__(16) float Ws[2][32 * WSS];  // [gate col][k] per buffer
    __shared__ float Gp[64 * 32];                    // group-1 partials
    __shared__ float Gs[64 * 33];                    // gates for cell update

    const int tid = threadIdx.x;
    const int sub = tid & 255;
    const int grp = tid >> 8;          // k-half of each slice
    const int tx = sub & 15;           // 2 cols
    const int ty = sub >> 4;           // 4 rows
    const int col_base = blockIdx.x * 8;
    const int kofs = grp * 16;

    // staging maps
    const int arow = tid >> 3;                 // 0..63
    const int ac0  = (tid & 7) * 4;
    const int wrow = tid >> 3;                 // (tid<256) 0..31
    const int wc   = (tid & 7) * 4;
    const int wgr  = (wrow >> 3) * Hn + col_base + (wrow & 7);

    const float* hin = g_h[insel];
    const int nIn = ENC ? (In / 32) : 0;
    const int nsl = nIn + Hn / 32;

    // per-thread global source address for slice s
    auto srcA = [&](int s) -> const float* {
        if (ENC && s < nIn)
            return xbase + (size_t)arow * ((long)Tn * In) + s * 32 + ac0;
        return hin + (size_t)arow * Hn + (s - nIn) * 32 + ac0;
    };
    auto srcW = [&](int s) -> const float* {
        if (ENC && s < nIn)
            return Wih + (size_t)wgr * In + s * 32 + wc;
        return Whh + (size_t)wgr * Hn + (s - nIn) * 32 + wc;
    };

    // prologue: stage slice 0 into buffer 0
    {
        float4 va = *(const float4*)srcA(0);
        *(float4*)&As[0][arow * 36 + ac0] = va;
        if (tid < 256) {
            float4 vw = *(const float4*)srcW(0);
            Ws[0][wrow * WSS + wc + 0] = vw.x;
            Ws[0][wrow * WSS + wc + 1] = vw.y;
            Ws[0][wrow * WSS + wc + 2] = vw.z;
            Ws[0][wrow * WSS + wc + 3] = vw.w;
        }
    }
    __syncthreads();

    unsigned long long acc[4][2] = {};   // each = (sum even k, sum odd k)

    for (int s = 0; s < nsl; ++s) {
        const int buf = s & 1;
        const bool pre = (s + 1 < nsl);
        float4 va, vw;
        if (pre) {                       // prefetch next slice into registers
            va = *(const float4*)srcA(s + 1);
            if (tid < 256) vw = *(const float4*)srcW(s + 1);
        }

        // compute this group's 16-k half: 8 iterations of 2 k
        const float* ab = &As[buf][kofs];
        const float* wb = &Ws[buf][kofs];
        #pragma unroll
        for (int k2 = 0; k2 < 8; ++k2) {
            const int kk = k2 * 2;
            unsigned long long a0 = *(const unsigned long long*)&ab[(ty * 4 + 0) * 36 + kk];
            unsigned long long a1 = *(const unsigned long long*)&ab[(ty * 4 + 1) * 36 + kk];
            unsigned long long a2 = *(const unsigned long long*)&ab[(ty * 4 + 2) * 36 + kk];
            unsigned long long a3 = *(const unsigned long long*)&ab[(ty * 4 + 3) * 36 + kk];
            unsigned long long b0 = *(const unsigned long long*)&wb[(tx * 2 + 0) * WSS + kk];
            unsigned long long b1 = *(const unsigned long long*)&wb[(tx * 2 + 1) * WSS + kk];
            FMA2(acc[0][0], a0, b0); FMA2(acc[0][1], a0, b1);
            FMA2(acc[1][0], a1, b0); FMA2(acc[1][1], a1, b1);
            FMA2(acc[2][0], a2, b0); FMA2(acc[2][1], a2, b1);
            FMA2(acc[3][0], a3, b0); FMA2(acc[3][1], a3, b1);
        }

        if (pre) {                       // write prefetched slice to other buffer
            *(float4*)&As[buf ^ 1][arow * 36 + ac0] = va;
            if (tid < 256) {
                Ws[buf ^ 1][wrow * WSS + wc + 0] = vw.x;
                Ws[buf ^ 1][wrow * WSS + wc + 1] = vw.y;
                Ws[buf ^ 1][wrow * WSS + wc + 2] = vw.z;
                Ws[buf ^ 1][wrow * WSS + wc + 3] = vw.w;
            }
        }
        __syncthreads();
    }

    // horizontal add of (even, odd) lanes
    float accf[4][2];
    #pragma unroll
    for (int i = 0; i < 4; i++)
        #pragma unroll
        for (int j = 0; j < 2; j++) {
            float lo, hi;
            asm("mov.b64 {%0,%1}, %2;" : "=f"(lo), "=f"(hi) : "l"(acc[i][j]));
            accf[i][j] = lo + hi;
        }

    // ---- combine group partials ----
    if (grp == 1) {
        #pragma unroll
        for (int i = 0; i < 4; i++)
            #pragma unroll
            for (int j = 0; j < 2; j++)
                Gp[(ty * 4 + i) * 32 + tx * 2 + j] = accf[i][j];
    }
    __syncthreads();

    if (grp == 0) {
        #pragma unroll
        for (int i = 0; i < 4; i++) {
            int r = ty * 4 + i;
            #pragma unroll
            for (int j = 0; j < 2; j++) {
                int oc = tx * 2 + j;
                int gr = (oc >> 3) * Hn + col_base + (oc & 7);
                float g = accf[i][j] + Gp[r * 32 + oc] + (ENC ? g_be[gr] : g_bd[gr]);
                if (!ENC) g += g_tokf[r] * g_sd[gr];   // rank-1 token-input term
                Gs[r * 33 + oc] = g;
            }
        }
    }
    __syncthreads();

    // ---- cell update: 512 (b, hc) pairs, one per thread ----
    const int outsel = insel ^ 1;
    {
        int b = tid >> 3;
        int hc = tid & 7;
        float gi = Gs[b * 33 + hc];
        float gf = Gs[b * 33 + 8 + hc];
        float gg = Gs[b * 33 + 16 + hc];
        float go = Gs[b * 33 + 24 + hc];
        int col = col_base + hc;
        float cprev = g_c[b * Hn + col];
        float cc = sigf(gf) * cprev + sigf(gi) * tanhf(gg);
        g_c[b * Hn + col] = cc;
        g_h[outsel][b * Hn + col] = sigf(go) * tanhf(cc);
    }
}

// fc partial GEMM: grid (32 oc-tiles of 16, 4 K-quarters), 256 threads.
__global__ __launch_bounds__(256) void fc_partial(const float* __restrict__ fcW, int hsel) {
    __shared__ float Ah[64 * 36];
    __shared__ float Wf[16 * 33];
    const int tid = threadIdx.x;
    const int tx = tid & 15;   // one output col each
    const int ty = tid >> 4;   // 4 batch rows each
    const int oc0 = blockIdx.x * 16;
    const int kq = blockIdx.y;
    const float* hin = g_h[hsel];
    float acc[4] = {};

    for (int k0 = kq * 256; k0 < kq * 256 + 256; k0 += 32) {
        {
            int row = tid >> 2;
            int c0 = (tid & 3) * 8;
            const float* src = hin + (size_t)row * Hn + k0 + c0;
            *(float4*)&Ah[row * 36 + c0]     = *(const float4*)(src);
            *(float4*)&Ah[row * 36 + c0 + 4] = *(const float4*)(src + 4);
        }
        if (tid < 128) {
            int wrow = tid >> 3;
            int wc = (tid & 7) * 4;
            float4 v = *(const float4*)(fcW + (size_t)(oc0 + wrow) * Hn + k0 + wc);
            Wf[wrow * 33 + wc + 0] = v.x;
            Wf[wrow * 33 + wc + 1] = v.y;
            Wf[wrow * 33 + wc + 2] = v.z;
            Wf[wrow * 33 + wc + 3] = v.w;
        }
        __syncthreads();
        #pragma unroll
        for (int kk = 0; kk < 32; ++kk) {
            float b = Wf[tx * 33 + kk];
            acc[0] += Ah[(ty * 4 + 0) * 36 + kk] * b;
            acc[1] += Ah[(ty * 4 + 1) * 36 + kk] * b;
            acc[2] += Ah[(ty * 4 + 2) * 36 + kk] * b;
            acc[3] += Ah[(ty * 4 + 3) * 36 + kk] * b;
        }
        __syncthreads();
    }
    #pragma unroll
    for (int i = 0; i < 4; i++)
        g_part[kq][(size_t)(ty * 4 + i) * On + oc0 + tx] = acc[i];
}

// argmax per batch row, first-index tie-break (matches jnp.argmax). f32 output.
__global__ __launch_bounds__(128) void argmax_kernel(const float* __restrict__ fcb,
                                                     float* __restrict__ out, int step) {
    const int b = blockIdx.x;
    const int tid = threadIdx.x;
    __shared__ float sv[128];
    __shared__ int si[128];
    float bestv = -3.4e38f;
    int besti = 0;
    for (int o = tid; o < On; o += 128) {
        float v = fcb[o] + g_part[0][(size_t)b * On + o] + g_part[1][(size_t)b * On + o]
                         + g_part[2][(size_t)b * On + o] + g_part[3][(size_t)b * On + o];
        if (v > bestv) { bestv = v; besti = o; }   // ascending o => first index kept
    }
    sv[tid] = bestv;
    si[tid] = besti;
    __syncthreads();
    for (int s = 64; s > 0; s >>= 1) {
        if (tid < s) {
            float v2 = sv[tid + s];
            int i2 = si[tid + s];
            if (v2 > sv[tid] || (v2 == sv[tid] && i2 < si[tid])) { sv[tid] = v2; si[tid] = i2; }
        }
        __syncthreads();
    }
    if (tid == 0) {
        g_tokf[b] = (float)si[0];
        out[b * NSTEPS + step] = (float)si[0];
    }
}

extern "C" void kernel_launch(void* const* d_in, const int* in_sizes, int n_in,
                              void* d_out, int out_size) {
    // Insertion-order binding (confirmed by diagnostics):
    const float* inputs  = (const float*)d_in[0];
    const float* enc_Wih = (const float*)d_in[1];
    const float* enc_Whh = (const float*)d_in[2];
    const float* enc_bih = (const float*)d_in[3];
    const float* enc_bhh = (const float*)d_in[4];
    const float* dec_Wih = (const float*)d_in[5];
    const float* dec_Whh = (const float*)d_in[6];
    const float* dec_bih = (const float*)d_in[7];
    const float* dec_bhh = (const float*)d_in[8];
    const float* fc_W    = (const float*)d_in[9];
    const float* fc_b    = (const float*)d_in[10];
    float* out = (float*)d_out;

    prep_kernel<<<256, 256>>>(enc_bih, enc_bhh, dec_bih, dec_bhh, dec_Wih);

    // encoder: 512 sequential steps; x_t rows are strided (inputs is [B, T, I])
    for (int t = 0; t < Tn; t++)
        lstm_step<true><<<128, 512>>>(enc_Wih, inputs + (size_t)t * In, enc_Whh, t & 1);

    // decoder: 100 autoregressive steps
    for (int s = 0; s < NSTEPS; s++) {
        lstm_step<false><<<128, 512>>>(nullptr, nullptr, dec_Whh, s & 1);
        fc_partial<<<dim3(32, 4), 256>>>(fc_W, (s & 1) ^ 1);
        argmax_kernel<<<64, 128>>>(fc_b, out, s);
    }
}